// round 2
// baseline (speedup 1.0000x reference)
#include <cuda_runtime.h>
#include <math.h>

#define Bsz 512
#define Tsz 512
#define FS 64
#define FC 32
#define H 256
#define LN_EPS 1e-5f

// Packed, transposed weights (k-major so warp loads are coalesced).
// Each float2 = {gate weight, "partner" weight} for one (k, j).
__device__ float2 g_pk_s0[FS * H];   // {Win0_seq[j,k], Wg0_seq[j,k]}
__device__ float2 g_pk_c0[FC * H];   // {Win0_ctx[j,k], Wg0_ctx[j,k]}
__device__ float2 g_pk_h0[H * H];    // {Wg0_h[j,k],   Wrec0[j,k]}
__device__ float2 g_pk_x1[H * H];    // {Win1[j,k],    Wg1_x[j,k]}
__device__ float2 g_pk_h1[H * H];    // {Wg1_h[j,k],   Wrec1[j,k]}

__global__ void setup_kernel(const float* __restrict__ Win0,
                             const float* __restrict__ Wrec0,
                             const float* __restrict__ Wg0,
                             const float* __restrict__ Win1,
                             const float* __restrict__ Wrec1,
                             const float* __restrict__ Wg1) {
    int j = threadIdx.x;   // 0..255 (output neuron)
    int k = blockIdx.x;    // 0..863 (k-row across all packed regions)
    if (k < 64) {
        g_pk_s0[k * H + j] = make_float2(Win0[j * 96 + k], Wg0[j * 352 + k]);
    } else if (k < 96) {
        int kk = k - 64;
        g_pk_c0[kk * H + j] = make_float2(Win0[j * 96 + 64 + kk], Wg0[j * 352 + 64 + kk]);
    } else if (k < 352) {
        int kk = k - 96;
        g_pk_h0[kk * H + j] = make_float2(Wg0[j * 352 + 96 + kk], Wrec0[j * H + kk]);
    } else if (k < 608) {
        int kk = k - 352;
        g_pk_x1[kk * H + j] = make_float2(Win1[j * H + kk], Wg1[j * 512 + kk]);
    } else {
        int kk = k - 608;
        g_pk_h1[kk * H + j] = make_float2(Wg1[j * 512 + 256 + kk], Wrec1[j * H + kk]);
    }
}

// Block-wide sum of 8 per-thread floats (256 threads). red must hold 64 floats.
__device__ __forceinline__ void block_reduce8(float v[8], float* red,
                                              int lane, int warp, float out[8]) {
#pragma unroll
    for (int off = 16; off > 0; off >>= 1) {
#pragma unroll
        for (int i = 0; i < 8; i++)
            v[i] += __shfl_xor_sync(0xffffffffu, v[i], off);
    }
    if (lane == 0) {
#pragma unroll
        for (int i = 0; i < 8; i++) red[warp * 8 + i] = v[i];
    }
    __syncthreads();
#pragma unroll
    for (int i = 0; i < 8; i++) out[i] = 0.f;
#pragma unroll
    for (int w = 0; w < 8; w++) {
#pragma unroll
        for (int i = 0; i < 8; i++) out[i] += red[w * 8 + i];
    }
    __syncthreads();
}

// RK4 integration of one LTC cell + LayerNorm + tanh. Thread j owns neuron j
// for 4 batch rows; state h[] lives in registers.
__device__ __forceinline__ void rk4_ln(const float2* __restrict__ pk,
                                       float4* hh, float* red,
                                       int j, int lane, int warp,
                                       float h[4], const float pin[4], const float pg[4],
                                       float invtau, float lng, float lnb) {
    float hs[4], kacc[4];
#pragma unroll
    for (int b = 0; b < 4; b++) hs[b] = h[b];
    const float cnext[4] = {0.5f, 0.5f, 1.0f, 0.0f};
    const float wk[4]    = {1.0f, 2.0f, 2.0f, 1.0f};

#pragma unroll
    for (int s = 0; s < 4; s++) {
        __syncthreads();   // previous-stage hh reads complete
        hh[j] = make_float4(hs[0], hs[1], hs[2], hs[3]);
        __syncthreads();   // hh fully written

        float ag[4], ar[4];
#pragma unroll
        for (int b = 0; b < 4; b++) { ag[b] = pg[b]; ar[b] = 0.f; }
#pragma unroll 8
        for (int k = 0; k < H; k++) {
            float2 w  = pk[k * H + j];   // coalesced LDG.64
            float4 hv = hh[k];           // LDS.128 broadcast
            ag[0] += w.x * hv.x; ar[0] += w.y * hv.x;
            ag[1] += w.x * hv.y; ar[1] += w.y * hv.y;
            ag[2] += w.x * hv.z; ar[2] += w.y * hv.z;
            ag[3] += w.x * hv.w; ar[3] += w.y * hv.w;
        }
#pragma unroll
        for (int b = 0; b < 4; b++) {
            float tg = tanhf(ag[b]);
            float g  = 1.f / (1.f + expf(-tg));
            float kb = pin[b] - hs[b] * invtau + g * ar[b];
            if (s == 0) kacc[b] = kb; else kacc[b] += wk[s] * kb;
            hs[b] = h[b] + cnext[s] * kb;
        }
    }

    float hn[4], v8[8];
#pragma unroll
    for (int b = 0; b < 4; b++) {
        hn[b]   = h[b] + kacc[b] * (1.f / 6.f);
        v8[b]   = hn[b];
        v8[4 + b] = hn[b] * hn[b];
    }
    float o8[8];
    block_reduce8(v8, red, lane, warp, o8);
#pragma unroll
    for (int b = 0; b < 4; b++) {
        float mu   = o8[b] * (1.f / (float)H);
        float var  = o8[4 + b] * (1.f / (float)H) - mu * mu;
        float rstd = rsqrtf(var + LN_EPS);
        h[b] = tanhf((hn[b] - mu) * rstd * lng + lnb);   // clip(-10,10) is a no-op
    }
}

__global__ __launch_bounds__(256)
void ltc_main(const float* __restrict__ seq,  const float* __restrict__ ctx,
              const float* __restrict__ tau0, const float* __restrict__ bg0,
              const float* __restrict__ lng0, const float* __restrict__ lnb0,
              const float* __restrict__ tau1, const float* __restrict__ bg1,
              const float* __restrict__ lng1, const float* __restrict__ lnb1,
              const float* __restrict__ cW1,  const float* __restrict__ cb1,
              const float* __restrict__ cW2,  const float* __restrict__ cb2,
              float* __restrict__ out) {
    __shared__ float4 hh[H];    // stage vector, [k] -> 4 batch rows
    __shared__ float4 xin[H];   // layer-1 input (layer-0 output)
    __shared__ float4 xs[FS];   // seq features at t (also ctx at init)
    __shared__ float  red[64];

    int j    = threadIdx.x;
    int lane = j & 31, warp = j >> 5;
    int b0   = blockIdx.x * 4;

    float invt0 = 1.f / (log1pf(expf(tau0[j])) + 1.f);
    float invt1 = 1.f / (log1pf(expf(tau1[j])) + 1.f);
    float lng0v = lng0[j], lnb0v = lnb0[j];
    float lng1v = lng1[j], lnb1v = lnb1[j];
    float rbg1  = bg1[j];

    // Context contributions to layer-0 pre-activations: constant over t.
    if (j < FC) {
        xs[j] = make_float4(ctx[(b0 + 0) * FC + j], ctx[(b0 + 1) * FC + j],
                            ctx[(b0 + 2) * FC + j], ctx[(b0 + 3) * FC + j]);
    }
    __syncthreads();
    float cwin[4], cg[4];
    {
        float bv = bg0[j];
#pragma unroll
        for (int b = 0; b < 4; b++) { cwin[b] = 0.f; cg[b] = bv; }
    }
#pragma unroll 4
    for (int k = 0; k < FC; k++) {
        float2 w  = g_pk_c0[k * H + j];
        float4 xv = xs[k];
        cwin[0] += w.x * xv.x; cg[0] += w.y * xv.x;
        cwin[1] += w.x * xv.y; cg[1] += w.y * xv.y;
        cwin[2] += w.x * xv.z; cg[2] += w.y * xv.z;
        cwin[3] += w.x * xv.w; cg[3] += w.y * xv.w;
    }
    __syncthreads();   // done with ctx in xs before reuse for seq

    float h0r[4] = {0.f, 0.f, 0.f, 0.f};
    float h1r[4] = {0.f, 0.f, 0.f, 0.f};

    const float* seqb0 = seq + (size_t)(b0 + 0) * Tsz * FS;
    const float* seqb1 = seq + (size_t)(b0 + 1) * Tsz * FS;
    const float* seqb2 = seq + (size_t)(b0 + 2) * Tsz * FS;
    const float* seqb3 = seq + (size_t)(b0 + 3) * Tsz * FS;

    for (int t = 0; t < Tsz; t++) {
        if (j < FS) {
            int o = t * FS + j;
            xs[j] = make_float4(seqb0[o], seqb1[o], seqb2[o], seqb3[o]);
        }
        __syncthreads();

        // ---- layer 0: per-timestep input projections (seq part) ----
        float pin[4], pg[4];
#pragma unroll
        for (int b = 0; b < 4; b++) { pin[b] = cwin[b]; pg[b] = cg[b]; }
#pragma unroll 8
        for (int k = 0; k < FS; k++) {
            float2 w  = g_pk_s0[k * H + j];
            float4 xv = xs[k];
            pin[0] += w.x * xv.x; pg[0] += w.y * xv.x;
            pin[1] += w.x * xv.y; pg[1] += w.y * xv.y;
            pin[2] += w.x * xv.z; pg[2] += w.y * xv.z;
            pin[3] += w.x * xv.w; pg[3] += w.y * xv.w;
        }
        rk4_ln(g_pk_h0, hh, red, j, lane, warp, h0r, pin, pg, invt0, lng0v, lnb0v);

        // ---- hand layer-0 output to layer 1 ----
        __syncthreads();
        xin[j] = make_float4(h0r[0], h0r[1], h0r[2], h0r[3]);
        __syncthreads();

        // ---- layer 1: per-timestep input projections ----
#pragma unroll
        for (int b = 0; b < 4; b++) { pin[b] = 0.f; pg[b] = rbg1; }
#pragma unroll 8
        for (int k = 0; k < H; k++) {
            float2 w  = g_pk_x1[k * H + j];
            float4 xv = xin[k];
            pin[0] += w.x * xv.x; pg[0] += w.y * xv.x;
            pin[1] += w.x * xv.y; pg[1] += w.y * xv.y;
            pin[2] += w.x * xv.z; pg[2] += w.y * xv.z;
            pin[3] += w.x * xv.w; pg[3] += w.y * xv.w;
        }
        rk4_ln(g_pk_h1, hh, red, j, lane, warp, h1r, pin, pg, invt1, lng1v, lnb1v);
    }

    // ---- head: out = relu(h1 @ cW1.T + cb1) @ cW2.T + cb2 ----
    __syncthreads();
    xin[j] = make_float4(h1r[0], h1r[1], h1r[2], h1r[3]);
    __syncthreads();

    float p[4] = {0.f, 0.f, 0.f, 0.f};
    if (j < 128) {
        float acc[4];
        float bb = cb1[j];
#pragma unroll
        for (int b = 0; b < 4; b++) acc[b] = bb;
#pragma unroll 8
        for (int k = 0; k < H; k++) {
            float  w  = cW1[j * H + k];
            float4 xv = xin[k];
            acc[0] += w * xv.x; acc[1] += w * xv.y;
            acc[2] += w * xv.z; acc[3] += w * xv.w;
        }
        float w2 = cW2[j];
#pragma unroll
        for (int b = 0; b < 4; b++) p[b] = fmaxf(acc[b], 0.f) * w2;
    }
    float v8[8], o8[8];
#pragma unroll
    for (int i = 0; i < 8; i++) v8[i] = (i < 4) ? p[i] : 0.f;
    block_reduce8(v8, red, lane, warp, o8);
    if (j < 4) out[b0 + j] = o8[j] + cb2[0];
}

extern "C" void kernel_launch(void* const* d_in, const int* in_sizes, int n_in,
                              void* d_out, int out_size) {
    const float* seq   = (const float*)d_in[0];
    const float* ctx   = (const float*)d_in[1];
    const float* tau0  = (const float*)d_in[2];
    const float* Win0  = (const float*)d_in[3];
    const float* Wrec0 = (const float*)d_in[4];
    const float* Wg0   = (const float*)d_in[5];
    const float* bg0   = (const float*)d_in[6];
    const float* lng0  = (const float*)d_in[7];
    const float* lnb0  = (const float*)d_in[8];
    const float* tau1  = (const float*)d_in[9];
    const float* Win1  = (const float*)d_in[10];
    const float* Wrec1 = (const float*)d_in[11];
    const float* Wg1   = (const float*)d_in[12];
    const float* bg1   = (const float*)d_in[13];
    const float* lng1  = (const float*)d_in[14];
    const float* lnb1  = (const float*)d_in[15];
    const float* cW1   = (const float*)d_in[16];
    const float* cb1   = (const float*)d_in[17];
    const float* cW2   = (const float*)d_in[18];
    const float* cb2   = (const float*)d_in[19];
    float* out = (float*)d_out;

    setup_kernel<<<864, 256>>>(Win0, Wrec0, Wg0, Win1, Wrec1, Wg1);
    ltc_main<<<128, 256>>>(seq, ctx, tau0, bg0, lng0, lnb0,
                           tau1, bg1, lng1, lnb1,
                           cW1, cb1, cW2, cb2, out);
}

// round 3
// speedup vs baseline: 1.6395x; 1.6395x over previous
#include <cuda_runtime.h>
#include <math.h>

#define Bsz 512
#define Tsz 512
#define FS 64
#define FC 32
#define H 256
#define LN_EPS 1e-5f

typedef unsigned long long ull;

// Packed, transposed weights (k-major so warp loads are coalesced).
// Each float2 = {matrix1[j,k], matrix2[j,k]} for one (k, j).
__device__ float2 g_pk_s0[FS * H];   // {Win0_seq, Wg0_seq}
__device__ float2 g_pk_c0[FC * H];   // {Win0_ctx, Wg0_ctx}
__device__ float2 g_pk_h0[H * H];    // {Wg0_h,    Wrec0}
__device__ float2 g_pk_x1[H * H];    // {Win1,     Wg1_x}
__device__ float2 g_pk_h1[H * H];    // {Wg1_h,    Wrec1}

__global__ void setup_kernel(const float* __restrict__ Win0,
                             const float* __restrict__ Wrec0,
                             const float* __restrict__ Wg0,
                             const float* __restrict__ Win1,
                             const float* __restrict__ Wrec1,
                             const float* __restrict__ Wg1) {
    int j = threadIdx.x;
    int k = blockIdx.x;
    if (k < 64) {
        g_pk_s0[k * H + j] = make_float2(Win0[j * 96 + k], Wg0[j * 352 + k]);
    } else if (k < 96) {
        int kk = k - 64;
        g_pk_c0[kk * H + j] = make_float2(Win0[j * 96 + 64 + kk], Wg0[j * 352 + 64 + kk]);
    } else if (k < 352) {
        int kk = k - 96;
        g_pk_h0[kk * H + j] = make_float2(Wg0[j * 352 + 96 + kk], Wrec0[j * H + kk]);
    } else if (k < 608) {
        int kk = k - 352;
        g_pk_x1[kk * H + j] = make_float2(Win1[j * H + kk], Wg1[j * 512 + kk]);
    } else {
        int kk = k - 608;
        g_pk_h1[kk * H + j] = make_float2(Wg1[j * 512 + 256 + kk], Wrec1[j * H + kk]);
    }
}

// ---- packed fp32x2 helpers (bit-identical to 2x fma.rn.f32) ----
__device__ __forceinline__ ull pk2(float a, float b) {
    ull r; asm("mov.b64 %0,{%1,%2};" : "=l"(r) : "f"(a), "f"(b)); return r;
}
__device__ __forceinline__ void up2(ull v, float& a, float& b) {
    asm("mov.b64 {%0,%1},%2;" : "=f"(a), "=f"(b) : "l"(v));
}
__device__ __forceinline__ void fma2(ull& d, ull a, ull b) {
    asm("fma.rn.f32x2 %0,%1,%2,%0;" : "+l"(d) : "l"(a), "l"(b));
}

// ---- pipelined dual-matvec: acc1 += M1^T hh, acc2 += M2^T hh (4 batch) ----
__device__ __forceinline__ void preload16(float2 w[16], const float2* __restrict__ pk,
                                          int kb, int j) {
#pragma unroll
    for (int i = 0; i < 16; i++) w[i] = pk[(kb + i) * H + j];
}

__device__ __forceinline__ void comp16(const float2 w[16],
                                       const ull* __restrict__ hhb, int kb,
                                       ull& a1_01, ull& a1_23, ull& a2_01, ull& a2_23) {
#pragma unroll
    for (int i = 0; i < 16; i++) {
        ulonglong2 h = *(const ulonglong2*)(hhb + (size_t)(kb + i) * 2);  // LDS.128 bcast
        ull wxx = pk2(w[i].x, w[i].x);
        ull wyy = pk2(w[i].y, w[i].y);
        fma2(a1_01, wxx, h.x); fma2(a1_23, wxx, h.y);
        fma2(a2_01, wyy, h.x); fma2(a2_23, wyy, h.y);
    }
}

// wA must hold the first 16 rows already (preloaded before the barrier).
template<int K>
__device__ __forceinline__ void matvec_rest(const float2* __restrict__ pk, int j,
                                            const ull* __restrict__ hhb, float2 wA[16],
                                            ull& a1_01, ull& a1_23, ull& a2_01, ull& a2_23) {
    float2 wB[16];
#pragma unroll 1
    for (int kb = 0; kb < K; kb += 32) {
        preload16(wB, pk, kb + 16, j);
        comp16(wA, hhb, kb, a1_01, a1_23, a2_01, a2_23);
        if (kb + 32 < K) preload16(wA, pk, kb + 32, j);
        comp16(wB, hhb, kb + 16, a1_01, a1_23, a2_01, a2_23);
    }
}

// Block-wide sum of 8 per-thread floats (256 threads). red holds 64 floats.
__device__ __forceinline__ void block_reduce8(float v[8], float* red,
                                              int lane, int warp, float out[8]) {
#pragma unroll
    for (int off = 16; off > 0; off >>= 1) {
#pragma unroll
        for (int i = 0; i < 8; i++)
            v[i] += __shfl_xor_sync(0xffffffffu, v[i], off);
    }
    if (lane == 0) {
#pragma unroll
        for (int i = 0; i < 8; i++) red[warp * 8 + i] = v[i];
    }
    __syncthreads();
#pragma unroll
    for (int i = 0; i < 8; i++) out[i] = 0.f;
#pragma unroll
    for (int w = 0; w < 8; w++) {
#pragma unroll
        for (int i = 0; i < 8; i++) out[i] += red[w * 8 + i];
    }
    __syncthreads();
}

// RK4 + LayerNorm + tanh for one layer. One barrier per stage (double-buffered hh).
__device__ __forceinline__ void rk4_ln(const float2* __restrict__ pk,
                                       ull (*hh2)[2 * H], float* red,
                                       int j, int lane, int warp,
                                       float h[4], const float pin[4], const float pg[4],
                                       float invtau, float lng, float lnb) {
    float hs[4], kacc[4];
#pragma unroll
    for (int b = 0; b < 4; b++) hs[b] = h[b];

#pragma unroll 1
    for (int s = 0; s < 4; s++) {
        float cn  = (s < 2) ? 0.5f : (s == 2 ? 1.0f : 0.0f);
        float wks = (s == 1 || s == 2) ? 2.0f : 1.0f;
        ull* hhb = hh2[s & 1];
        *(ulonglong2*)&hhb[2 * j] =
            make_ulonglong2(pk2(hs[0], hs[1]), pk2(hs[2], hs[3]));
        float2 wA[16];
        preload16(wA, pk, 0, j);       // hoisted above the barrier: no hh dependence
        __syncthreads();               // hh fully written (prev reads covered by prev sync)

        ull ag01 = pk2(pg[0], pg[1]), ag23 = pk2(pg[2], pg[3]);
        ull ar01 = 0ull, ar23 = 0ull;
        matvec_rest<H>(pk, j, hhb, wA, ag01, ag23, ar01, ar23);

        float ag[4], ar[4];
        up2(ag01, ag[0], ag[1]); up2(ag23, ag[2], ag[3]);
        up2(ar01, ar[0], ar[1]); up2(ar23, ar[2], ar[3]);
#pragma unroll
        for (int b = 0; b < 4; b++) {
            float tg = tanhf(ag[b]);
            float g  = 1.f / (1.f + expf(-tg));
            float kb = pin[b] - hs[b] * invtau + g * ar[b];
            if (s == 0) kacc[b] = kb; else kacc[b] += wks * kb;
            hs[b] = h[b] + cn * kb;
        }
    }

    float hn[4], v8[8];
#pragma unroll
    for (int b = 0; b < 4; b++) {
        hn[b]     = h[b] + kacc[b] * (1.f / 6.f);
        v8[b]     = hn[b];
        v8[4 + b] = hn[b] * hn[b];
    }
    float o8[8];
    block_reduce8(v8, red, lane, warp, o8);
#pragma unroll
    for (int b = 0; b < 4; b++) {
        float mu   = o8[b] * (1.f / (float)H);
        float var  = o8[4 + b] * (1.f / (float)H) - mu * mu;
        float rstd = rsqrtf(var + LN_EPS);
        h[b] = tanhf((hn[b] - mu) * rstd * lng + lnb);   // clip(-10,10) is a no-op
    }
}

__global__ __launch_bounds__(256)
void ltc_main(const float* __restrict__ seq,  const float* __restrict__ ctx,
              const float* __restrict__ tau0, const float* __restrict__ bg0,
              const float* __restrict__ lng0, const float* __restrict__ lnb0,
              const float* __restrict__ tau1, const float* __restrict__ bg1,
              const float* __restrict__ lng1, const float* __restrict__ lnb1,
              const float* __restrict__ cW1,  const float* __restrict__ cb1,
              const float* __restrict__ cW2,  const float* __restrict__ cb2,
              float* __restrict__ out) {
    __shared__ __align__(16) ull hh2[2][2 * H];   // stage vector, batch-paired
    __shared__ __align__(16) ull xin2[2 * H];     // layer-1 input
    __shared__ __align__(16) ull xs2[2 * FS];     // seq features at t (ctx at init)
    __shared__ float red[64];

    int j    = threadIdx.x;
    int lane = j & 31, warp = j >> 5;
    int b0   = blockIdx.x * 4;

    float invt0 = 1.f / (log1pf(expf(tau0[j])) + 1.f);
    float invt1 = 1.f / (log1pf(expf(tau1[j])) + 1.f);
    float lng0v = lng0[j], lnb0v = lnb0[j];
    float lng1v = lng1[j], lnb1v = lnb1[j];
    float rbg1  = bg1[j];

    // ---- context contributions to layer-0 pre-activations (constant over t) ----
    if (j < FC) {
        float c0 = ctx[(b0 + 0) * FC + j], c1 = ctx[(b0 + 1) * FC + j];
        float c2 = ctx[(b0 + 2) * FC + j], c3 = ctx[(b0 + 3) * FC + j];
        *(ulonglong2*)&xs2[2 * j] = make_ulonglong2(pk2(c0, c1), pk2(c2, c3));
    }
    __syncthreads();
    float cwin[4], cg[4];
    {
        float bv = bg0[j];
#pragma unroll
        for (int b = 0; b < 4; b++) { cwin[b] = 0.f; cg[b] = bv; }
    }
#pragma unroll 4
    for (int k = 0; k < FC; k++) {
        float2 w = g_pk_c0[k * H + j];
        float x0, x1, x2, x3;
        up2(xs2[2 * k], x0, x1); up2(xs2[2 * k + 1], x2, x3);
        cwin[0] += w.x * x0; cg[0] += w.y * x0;
        cwin[1] += w.x * x1; cg[1] += w.y * x1;
        cwin[2] += w.x * x2; cg[2] += w.y * x2;
        cwin[3] += w.x * x3; cg[3] += w.y * x3;
    }
    __syncthreads();   // done with ctx in xs2 before reuse for seq

    float h0r[4] = {0.f, 0.f, 0.f, 0.f};
    float h1r[4] = {0.f, 0.f, 0.f, 0.f};

    const float* seqb0 = seq + (size_t)(b0 + 0) * Tsz * FS;
    const float* seqb1 = seq + (size_t)(b0 + 1) * Tsz * FS;
    const float* seqb2 = seq + (size_t)(b0 + 2) * Tsz * FS;
    const float* seqb3 = seq + (size_t)(b0 + 3) * Tsz * FS;

    // prefetch t=0 seq features
    float sq[4] = {0.f, 0.f, 0.f, 0.f};
    if (j < FS) {
        sq[0] = seqb0[j]; sq[1] = seqb1[j]; sq[2] = seqb2[j]; sq[3] = seqb3[j];
    }

#pragma unroll 1
    for (int t = 0; t < Tsz; t++) {
        if (j < FS)
            *(ulonglong2*)&xs2[2 * j] =
                make_ulonglong2(pk2(sq[0], sq[1]), pk2(sq[2], sq[3]));
        float2 wA[16];
        preload16(wA, g_pk_s0, 0, j);   // hoisted above barrier
        __syncthreads();

        // prefetch t+1 seq features (full timestep of latency to hide)
        if (j < FS) {
            int tn = (t + 1 < Tsz) ? t + 1 : t;
            int o  = tn * FS + j;
            sq[0] = seqb0[o]; sq[1] = seqb1[o]; sq[2] = seqb2[o]; sq[3] = seqb3[o];
        }

        // ---- layer 0 input projection (seq part; ctx folded into cwin/cg) ----
        ull p01 = pk2(cwin[0], cwin[1]), p23 = pk2(cwin[2], cwin[3]);
        ull g01 = pk2(cg[0],   cg[1]),   g23 = pk2(cg[2],   cg[3]);
        matvec_rest<FS>(g_pk_s0, j, xs2, wA, p01, p23, g01, g23);
        float pin[4], pg[4];
        up2(p01, pin[0], pin[1]); up2(p23, pin[2], pin[3]);
        up2(g01, pg[0],  pg[1]);  up2(g23, pg[2],  pg[3]);

        rk4_ln(g_pk_h0, hh2, red, j, lane, warp, h0r, pin, pg, invt0, lng0v, lnb0v);

        // ---- hand layer-0 output to layer 1 ----
        *(ulonglong2*)&xin2[2 * j] =
            make_ulonglong2(pk2(h0r[0], h0r[1]), pk2(h0r[2], h0r[3]));
        preload16(wA, g_pk_x1, 0, j);   // hoisted above barrier
        __syncthreads();

        // ---- layer 1 input projection ----
        p01 = 0ull; p23 = 0ull;
        g01 = pk2(rbg1, rbg1); g23 = g01;
        matvec_rest<H>(g_pk_x1, j, xin2, wA, p01, p23, g01, g23);
        up2(p01, pin[0], pin[1]); up2(p23, pin[2], pin[3]);
        up2(g01, pg[0],  pg[1]);  up2(g23, pg[2],  pg[3]);

        rk4_ln(g_pk_h1, hh2, red, j, lane, warp, h1r, pin, pg, invt1, lng1v, lnb1v);
    }

    // ---- head: out = relu(h1 @ cW1.T + cb1) @ cW2.T + cb2 ----
    *(ulonglong2*)&xin2[2 * j] =
        make_ulonglong2(pk2(h1r[0], h1r[1]), pk2(h1r[2], h1r[3]));
    __syncthreads();

    float p[4] = {0.f, 0.f, 0.f, 0.f};
    if (j < 128) {
        float acc[4];
        float bb = cb1[j];
#pragma unroll
        for (int b = 0; b < 4; b++) acc[b] = bb;
#pragma unroll 8
        for (int k = 0; k < H; k++) {
            float w = cW1[j * H + k];
            float x0, x1, x2, x3;
            up2(xin2[2 * k], x0, x1); up2(xin2[2 * k + 1], x2, x3);
            acc[0] += w * x0; acc[1] += w * x1;
            acc[2] += w * x2; acc[3] += w * x3;
        }
        float w2 = cW2[j];
#pragma unroll
        for (int b = 0; b < 4; b++) p[b] = fmaxf(acc[b], 0.f) * w2;
    }
    float v8[8], o8[8];
#pragma unroll
    for (int i = 0; i < 8; i++) v8[i] = (i < 4) ? p[i] : 0.f;
    block_reduce8(v8, red, lane, warp, o8);
    if (j < 4) out[b0 + j] = o8[j] + cb2[0];
}

extern "C" void kernel_launch(void* const* d_in, const int* in_sizes, int n_in,
                              void* d_out, int out_size) {
    const float* seq   = (const float*)d_in[0];
    const float* ctx   = (const float*)d_in[1];
    const float* tau0  = (const float*)d_in[2];
    const float* Win0  = (const float*)d_in[3];
    const float* Wrec0 = (const float*)d_in[4];
    const float* Wg0   = (const float*)d_in[5];
    const float* bg0   = (const float*)d_in[6];
    const float* lng0  = (const float*)d_in[7];
    const float* lnb0  = (const float*)d_in[8];
    const float* tau1  = (const float*)d_in[9];
    const float* Win1  = (const float*)d_in[10];
    const float* Wrec1 = (const float*)d_in[11];
    const float* Wg1   = (const float*)d_in[12];
    const float* bg1   = (const float*)d_in[13];
    const float* lng1  = (const float*)d_in[14];
    const float* lnb1  = (const float*)d_in[15];
    const float* cW1   = (const float*)d_in[16];
    const float* cb1   = (const float*)d_in[17];
    const float* cW2   = (const float*)d_in[18];
    const float* cb2   = (const float*)d_in[19];
    float* out = (float*)d_out;

    setup_kernel<<<864, 256>>>(Win0, Wrec0, Wg0, Win1, Wrec1, Wg1);
    ltc_main<<<128, 256>>>(seq, ctx, tau0, bg0, lng0, lnb0,
                           tau1, bg1, lng1, lnb1,
                           cW1, cb1, cW2, cb2, out);
}